// round 3
// baseline (speedup 1.0000x reference)
#include <cuda_runtime.h>
#include <cuda_bf16.h>

#define H           128
#define BASKET_LEN  200
#define NT          1024
#define GW          16          // gather warps
#define IPW         13          // items per gather warp (16*13 = 208 >= 200)

__device__ __forceinline__ float fast_sigmoid(float x) {
    return __fdividef(1.0f, 1.0f + __expf(-x));
}
__device__ __forceinline__ float fast_tanh(float x) {
    const float t = __expf(-2.0f * x);
    return __fdividef(1.0f - t, 1.0f + t);
}

__global__ __launch_bounds__(NT, 1)
void encoder_rnn_onecta(const int* __restrict__ basket,
                        const float* __restrict__ hidden,
                        const float* __restrict__ emb_table,
                        const float* __restrict__ w_ih,
                        const float* __restrict__ w_hh,
                        const float* __restrict__ b_ih,
                        const float* __restrict__ b_hh,
                        float* __restrict__ out,
                        int out_size)
{
    __shared__ float s_red[GW * H];   // gather partials, one row per gather warp
    __shared__ float s_emb[H];
    __shared__ float s_h[H];
    __shared__ float s_gi[3 * H];
    __shared__ float s_gh[3 * H];

    const int tid  = threadIdx.x;
    const int lane = tid & 31;
    const int w    = tid >> 5;

    if (w < GW) {
        // ================= Gather warps: 13 items each, MLP=13 =================
        const int item0 = w * IPW;
        int myidx = -1;
        if (lane < IPW && item0 + lane < BASKET_LEN)
            myidx = __ldg(&basket[item0 + lane]);

        float4 acc = make_float4(0.f, 0.f, 0.f, 0.f);
        #pragma unroll
        for (int i = 0; i < IPW; i++) {
            const int idx = __shfl_sync(0xFFFFFFFFu, myidx, i);
            if (idx >= 0) {
                const float4 v = __ldg(&reinterpret_cast<const float4*>(emb_table)[(size_t)idx * 32 + lane]);
                acc.x += v.x; acc.y += v.y; acc.z += v.z; acc.w += v.w;
            }
        }
        reinterpret_cast<float4*>(s_red)[w * 32 + lane] = acc;
    } else {
        // ================= gh warps: 24 rows each (two 12-row chunks) ==========
        const float4 h4 = __ldg(&reinterpret_cast<const float4*>(hidden)[lane]);
        const int rbase = (w - GW) * 24;          // 16 warps * 24 = 384 rows

        #pragma unroll
        for (int c = 0; c < 2; c++) {
            const int r0 = rbase + c * 12;
            float p[12];
            #pragma unroll
            for (int j = 0; j < 12; j++) {
                const float4 a = __ldg(&reinterpret_cast<const float4*>(w_hh)[(size_t)(r0 + j) * 32 + lane]);
                p[j] = a.x * h4.x + a.y * h4.y + a.z * h4.z + a.w * h4.w;
            }
            #pragma unroll
            for (int off = 16; off; off >>= 1)
                #pragma unroll
                for (int j = 0; j < 12; j++)
                    p[j] += __shfl_xor_sync(0xFFFFFFFFu, p[j], off);
            #pragma unroll
            for (int j = 0; j < 12; j++)
                if (lane == j) s_gh[r0 + j] = p[j] + __ldg(&b_hh[r0 + j]);
        }
    }
    __syncthreads();

    // ================= emb reduce + h stage (128 threads) ======================
    if (tid < H) {
        float a = 0.f;
        #pragma unroll
        for (int ww = 0; ww < GW; ww++) a += s_red[ww * H + tid];
        s_emb[tid] = a * (1.0f / (float)H);
        s_h[tid]   = hidden[tid];
    }
    __syncthreads();

    // ================= gi: all 32 warps, 12 rows each ==========================
    {
        const float4 e4 = reinterpret_cast<const float4*>(s_emb)[lane];
        const int r0 = w * 12;                    // 32 * 12 = 384 rows
        float p[12];
        #pragma unroll
        for (int j = 0; j < 12; j++) {
            const float4 a = __ldg(&reinterpret_cast<const float4*>(w_ih)[(size_t)(r0 + j) * 32 + lane]);
            p[j] = a.x * e4.x + a.y * e4.y + a.z * e4.z + a.w * e4.w;
        }
        #pragma unroll
        for (int off = 16; off; off >>= 1)
            #pragma unroll
            for (int j = 0; j < 12; j++)
                p[j] += __shfl_xor_sync(0xFFFFFFFFu, p[j], off);
        #pragma unroll
        for (int j = 0; j < 12; j++)
            if (lane == j) s_gi[r0 + j] = p[j] + __ldg(&b_ih[r0 + j]);
    }
    __syncthreads();

    // ================= gates + replicated output ===============================
    if (tid < H) {
        const float i_r = s_gi[tid];
        const float i_z = s_gi[H + tid];
        const float i_n = s_gi[2 * H + tid];
        const float h_r = s_gh[tid];
        const float h_z = s_gh[H + tid];
        const float h_n = s_gh[2 * H + tid];

        const float r = fast_sigmoid(i_r + h_r);
        const float z = fast_sigmoid(i_z + h_z);
        const float n = fast_tanh(i_n + r * h_n);
        const float h_new = (1.0f - z) * n + z * s_h[tid];

        for (int o = tid; o < out_size; o += H)
            out[o] = h_new;
    }
}

extern "C" void kernel_launch(void* const* d_in, const int* in_sizes, int n_in,
                              void* d_out, int out_size)
{
    const int*   basket    = (const int*)  d_in[0];
    const float* hidden    = (const float*)d_in[1];
    const float* emb_table = (const float*)d_in[2];
    const float* w_ih      = (const float*)d_in[3];
    const float* w_hh      = (const float*)d_in[4];
    const float* b_ih      = (const float*)d_in[5];
    const float* b_hh      = (const float*)d_in[6];
    float* out = (float*)d_out;

    encoder_rnn_onecta<<<1, NT>>>(basket, hidden, emb_table,
                                  w_ih, w_hh, b_ih, b_hh,
                                  out, out_size);
}

// round 5
// speedup vs baseline: 1.0172x; 1.0172x over previous
#include <cuda_runtime.h>
#include <cuda_bf16.h>

#define H            128
#define BASKET_LEN   200
#define NT           1024
#define GATHER_BLKS  7
#define IPB          29                 // items per gather block (7*29 = 203 >= 200)
#define NB           (GATHER_BLKS + 1)  // + gh block

// Device-global scratch (no allocation). Every slot rewritten each launch.
__device__ float        g_gi[GATHER_BLKS][3 * H];  // per-block partial w_ih @ S_b
__device__ float        g_gh[3 * H];
__device__ unsigned int g_ticket;                  // zero-init; reset each launch

__device__ __forceinline__ float fast_sigmoid(float x) {
    return __fdividef(1.0f, 1.0f + __expf(-x));
}
__device__ __forceinline__ float fast_tanh(float x) {
    const float t = __expf(-2.0f * x);
    return __fdividef(1.0f - t, 1.0f + t);
}

__global__ __launch_bounds__(NT, 1)
void encoder_rnn_dist(const int* __restrict__ basket,
                      const float* __restrict__ hidden,
                      const float* __restrict__ emb_table,
                      const float* __restrict__ w_ih,
                      const float* __restrict__ w_hh,
                      const float* __restrict__ b_ih,
                      const float* __restrict__ b_hh,
                      float* __restrict__ out,
                      int out_size)
{
    __shared__ float s_red[32 * H];     // 16 KB gather rows
    __shared__ float s_emb[H];          // per-block partial sum (unscaled)
    __shared__ float s_gi[3 * H];
    __shared__ float s_gh[3 * H];
    __shared__ float s_h[H];
    __shared__ unsigned s_last;

    const int tid  = threadIdx.x;
    const int lane = tid & 31;
    const int w    = tid >> 5;
    const int blk  = blockIdx.x;

    if (blk < GATHER_BLKS) {
        // ---- gather: one warp per item, whole 512B row in one LDG.128 ----
        const int item = blk * IPB + w;              // w: 0..31, use w < IPB
        float4 v = make_float4(0.f, 0.f, 0.f, 0.f);
        if (w < IPB && item < BASKET_LEN) {
            int idx = 0;
            if (lane == 0) idx = __ldg(&basket[item]);
            idx = __shfl_sync(0xFFFFFFFFu, idx, 0);
            v = __ldg(&reinterpret_cast<const float4*>(emb_table)[(size_t)idx * 32 + lane]);
        }
        reinterpret_cast<float4*>(s_red)[w * 32 + lane] = v;
        __syncthreads();

        // ---- partial sum S_b ----
        if (tid < H) {
            float a = 0.f;
            #pragma unroll
            for (int ww = 0; ww < IPB; ww++) a += s_red[ww * H + tid];
            s_emb[tid] = a;
        }
        __syncthreads();

        // ---- partial gi_b = w_ih @ S_b (32 warps x 12 rows) ----
        {
            const float4 e4 = reinterpret_cast<const float4*>(s_emb)[lane];
            const int r0 = w * 12;
            float p[12];
            #pragma unroll
            for (int j = 0; j < 12; j++) {
                const float4 a = __ldg(&reinterpret_cast<const float4*>(w_ih)[(size_t)(r0 + j) * 32 + lane]);
                p[j] = a.x * e4.x + a.y * e4.y + a.z * e4.z + a.w * e4.w;
            }
            #pragma unroll
            for (int off = 16; off; off >>= 1)
                #pragma unroll
                for (int j = 0; j < 12; j++)
                    p[j] += __shfl_xor_sync(0xFFFFFFFFu, p[j], off);
            #pragma unroll
            for (int j = 0; j < 12; j++)
                if (lane == j) g_gi[blk][r0 + j] = p[j];
        }
    } else {
        // ---- gh = w_hh @ h + b_hh (32 warps x 12 rows) ----
        const float4 h4 = __ldg(&reinterpret_cast<const float4*>(hidden)[lane]);
        const int r0 = w * 12;
        float p[12];
        #pragma unroll
        for (int j = 0; j < 12; j++) {
            const float4 a = __ldg(&reinterpret_cast<const float4*>(w_hh)[(size_t)(r0 + j) * 32 + lane]);
            p[j] = a.x * h4.x + a.y * h4.y + a.z * h4.z + a.w * h4.w;
        }
        #pragma unroll
        for (int off = 16; off; off >>= 1)
            #pragma unroll
            for (int j = 0; j < 12; j++)
                p[j] += __shfl_xor_sync(0xFFFFFFFFu, p[j], off);
        #pragma unroll
        for (int j = 0; j < 12; j++)
            if (lane == j) g_gh[r0 + j] = p[j] + __ldg(&b_hh[r0 + j]);
    }

    // ---- last-arriving block runs the (cheap) tail ----
    __threadfence();
    __syncthreads();
    if (tid == 0) s_last = (atomicAdd(&g_ticket, 1u) == NB - 1);
    __syncthreads();
    if (!s_last) return;
    __threadfence();   // acquire

    // ---- combine: gi = (1/H) * sum_b gi_b + b_ih ; stage gh, h ----
    if (tid < 3 * H) {
        float a = 0.f;
        #pragma unroll
        for (int b = 0; b < GATHER_BLKS; b++) a += g_gi[b][tid];
        s_gi[tid] = a * (1.0f / (float)H) + __ldg(&b_ih[tid]);
        s_gh[tid] = g_gh[tid];
    }
    if (tid < H) s_h[tid] = hidden[tid];
    __syncthreads();

    // ---- gates + replicated output ----
    if (tid < H) {
        const float r = fast_sigmoid(s_gi[tid]         + s_gh[tid]);
        const float z = fast_sigmoid(s_gi[H + tid]     + s_gh[H + tid]);
        const float n = fast_tanh  (s_gi[2 * H + tid] + r * s_gh[2 * H + tid]);
        const float h_new = (1.0f - z) * n + z * s_h[tid];
        for (int o = tid; o < out_size; o += H)
            out[o] = h_new;
    }

    if (tid == 0) g_ticket = 0;   // reset for next replay
}

extern "C" void kernel_launch(void* const* d_in, const int* in_sizes, int n_in,
                              void* d_out, int out_size)
{
    const int*   basket    = (const int*)  d_in[0];
    const float* hidden    = (const float*)d_in[1];
    const float* emb_table = (const float*)d_in[2];
    const float* w_ih      = (const float*)d_in[3];
    const float* w_hh      = (const float*)d_in[4];
    const float* b_ih      = (const float*)d_in[5];
    const float* b_hh      = (const float*)d_in[6];
    float* out = (float*)d_out;

    encoder_rnn_dist<<<NB, NT>>>(basket, hidden, emb_table,
                                 w_ih, w_hh, b_ih, b_hh,
                                 out, out_size);
}